// round 8
// baseline (speedup 1.0000x reference)
#include <cuda_runtime.h>
#include <math.h>

#define BB 4
#define TT 16
#define HH 64
#define WW 64
#define CIN 32
#define COUT 64
#define GG (4*COUT)   // 256 gate channels

typedef unsigned long long u64;

// Scratch: gx for all (b,t) pixels: (B*T*H*W, 256) floats = 268MB
__device__ float g_gx[(size_t)BB*TT*HH*WW*GG];
// Duplicated ping-pong hidden state: each channel stored as {h,h} pair
__device__ float g_h0d[(size_t)BB*HH*WW*COUT*2];
__device__ float g_h1d[(size_t)BB*HH*WW*COUT*2];
// Cell state
__device__ float g_c [(size_t)BB*HH*WW*COUT];
// Split transposed weights: [k][ci][lane(32)][4 floats]
// g01: {g0c0,g0c1,g1c0,g1c1}   g23: {g2c0,g2c1,g3c0,g3c1}   (c0=2*lane)
__device__ float g_rw01[9*COUT*32*4];
__device__ float g_rw23[9*COUT*32*4];
__device__ float g_wk01[9*CIN*32*4];
__device__ float g_wk23[9*CIN*32*4];

__device__ __forceinline__ float hsig(float z) {
    return fminf(fmaxf(0.2f*z + 0.5f, 0.0f), 1.0f);
}

__device__ __forceinline__ void fma_x2(u64& acc, u64 s, u64 w) {
    asm("fma.rn.f32x2 %0, %1, %2, %3;" : "=l"(acc) : "l"(s), "l"(w), "l"(acc));
}
__device__ __forceinline__ u64 pack2(float s) {
    u64 r;
    asm("mov.b64 %0, {%1, %1};" : "=l"(r) : "f"(s));
    return r;
}
__device__ __forceinline__ float2 unpack2(u64 v) {
    float2 f;
    asm("mov.b64 {%0, %1}, %2;" : "=f"(f.x), "=f"(f.y) : "l"(v));
    return f;
}

// ---------------------------------------------------------------------------
// Weight transpose prep.
// ---------------------------------------------------------------------------
__global__ __launch_bounds__(128)
void prep_weights(const float* __restrict__ wk, const float* __restrict__ rw)
{
    const int i = blockIdx.x * 128 + threadIdx.x;
    if (i < 9*COUT*32) {
        const int j  = i & 31;
        const int ci = (i >> 5) & 63;
        const int k  = i >> 11;
        const float* s = rw + ((size_t)(k*COUT + ci))*GG + 2*j;
        ((float4*)g_rw01)[i] = make_float4(s[0],   s[1],   s[64],  s[65]);
        ((float4*)g_rw23)[i] = make_float4(s[128], s[129], s[192], s[193]);
    }
    const int m = i - 9*COUT*32;
    if (m >= 0 && m < 9*CIN*32) {
        const int j  = m & 31;
        const int ci = (m >> 5) & 31;
        const int k  = m >> 10;
        const float* s = wk + ((size_t)(k*CIN + ci))*GG + 2*j;
        ((float4*)g_wk01)[m] = make_float4(s[0],   s[1],   s[64],  s[65]);
        ((float4*)g_wk23)[m] = make_float4(s[128], s[129], s[192], s[193]);
    }
}

// ---------------------------------------------------------------------------
// Phase 1: input-to-gate conv (unchanged from round 7 — occupancy is fine
// there thanks to the 8192-block grid).
// ---------------------------------------------------------------------------
__global__ __launch_bounds__(128, 4)
void input_conv_kernel(const float* __restrict__ x,
                       const float* __restrict__ bias)
{
    const int tx   = threadIdx.x;
    const int lane = tx & 31;
    const int co0  = lane * 2;
    const int pg   = tx >> 5;
    const int bid  = blockIdx.x;
    const int bt   = bid >> 7;
    const int r    = bid & 127;
    const int py   = r >> 1;
    const int px0  = (r & 1) * 32 + pg * 8;
    const bool okL = (px0 > 0);
    const bool okR = (px0 < WW - 8);

    u64 acc[4][8];
    #pragma unroll
    for (int g = 0; g < 4; g++) {
        u64 bv = *(const u64*)(bias + g*COUT + co0);
        #pragma unroll
        for (int p = 0; p < 8; p++) acc[g][p] = bv;
    }

    #pragma unroll
    for (int ky = 0; ky < 3; ky++) {
        const int iy = py + ky - 1;
        if ((unsigned)iy >= HH) continue;
        const float* __restrict__ xrow = x + ((size_t)(bt*HH + iy)*WW)*CIN;
        #pragma unroll 1
        for (int ci = 0; ci < CIN; ci++) {
            u64 hv2[10];
            hv2[0] = okL ? pack2(xrow[(size_t)(px0-1)*CIN + ci]) : 0ULL;
            #pragma unroll
            for (int j = 1; j < 9; j++)
                hv2[j] = pack2(xrow[(size_t)(px0-1+j)*CIN + ci]);
            hv2[9] = okR ? pack2(xrow[(size_t)(px0+8)*CIN + ci]) : 0ULL;
            #pragma unroll
            for (int kx = 0; kx < 3; kx++) {
                const size_t widx = ((size_t)(ky*3+kx)*CIN + ci)*32 + lane;
                ulonglong2 wA = ((const ulonglong2*)g_wk01)[widx];
                ulonglong2 wB = ((const ulonglong2*)g_wk23)[widx];
                #pragma unroll
                for (int p = 0; p < 8; p++) {
                    const u64 s2 = hv2[p + kx];
                    fma_x2(acc[0][p], s2, wA.x);
                    fma_x2(acc[1][p], s2, wA.y);
                    fma_x2(acc[2][p], s2, wB.x);
                    fma_x2(acc[3][p], s2, wB.y);
                }
            }
        }
    }

    const size_t rowbase = ((size_t)bt*HH + py)*WW;
    #pragma unroll
    for (int p = 0; p < 8; p++) {
        float* __restrict__ o = g_gx + (rowbase + px0 + p)*GG + co0;
        *(u64*)(o + 0*COUT) = acc[0][p];
        *(u64*)(o + 1*COUT) = acc[1][p];
        *(u64*)(o + 2*COUT) = acc[2][p];
        *(u64*)(o + 3*COUT) = acc[3][p];
    }
}

// ---------------------------------------------------------------------------
// Phase 2: one recurrent step, GATE-SPLIT.
// Block: 256 thr = 2 roles x 4 px-groups x 32 lanes. 32 px per block.
//   role 0 (warps 0-3): gates i,f   role 1 (warps 4-7): gates cc,o
// Each thread: 8 px x 2 ch x 2 gates = 16 packed accumulators.
// role 1 deposits accs in smem; role 0 runs the LSTM epilogue.
// Grid: B*H*2 = 512 -> 131072 threads (2x round 7).
// ---------------------------------------------------------------------------
template<bool FIRST>
__global__ __launch_bounds__(256, 3)
void step_kernel(float* __restrict__ y,
                 const int t,
                 const float* __restrict__ gamma,
                 const float* __restrict__ beta,
                 const float* __restrict__ mmean,
                 const float* __restrict__ mvar)
{
    __shared__ u64 sh[4][32][16];   // [pg][lane][gate*8+px] from role 1

    const float* __restrict__ hprevd = (t & 1) ? g_h0d : g_h1d;
    float*       __restrict__ hnewd  = (t & 1) ? g_h1d : g_h0d;

    const int tx   = threadIdx.x;
    const int lane = tx & 31;
    const int co0  = lane * 2;
    const int wid  = tx >> 5;
    const int role = wid >> 2;               // 0: gates 0,1   1: gates 2,3
    const int pg   = wid & 3;
    const int bid  = blockIdx.x;
    const int b    = bid >> 7;
    const int r    = bid & 127;
    const int py   = r >> 1;
    const int px0  = (r & 1) * 32 + pg * 8;
    const bool okL = (px0 > 0);
    const bool okR = (px0 < WW - 8);

    u64 acc[2][8];                            // [gate within role][pixel]
    const size_t gxrow = ((size_t)(b*TT + t)*HH + py)*WW;
    const int g0 = role * 2;
    #pragma unroll
    for (int p = 0; p < 8; p++) {
        const float* __restrict__ gp = g_gx + (gxrow + px0 + p)*GG + co0;
        acc[0][p] = *(const u64*)(gp + (g0+0)*COUT);
        acc[1][p] = *(const u64*)(gp + (g0+1)*COUT);
    }

    if (!FIRST) {
        const float* __restrict__ wbase = role ? g_rw23 : g_rw01;
        #pragma unroll
        for (int ky = 0; ky < 3; ky++) {
            const int iy = py + ky - 1;
            if ((unsigned)iy >= HH) continue;
            const float* __restrict__ hrow = hprevd + ((size_t)(b*HH + iy)*WW)*(COUT*2);
            #pragma unroll 1
            for (int ci = 0; ci < COUT; ci++) {
                u64 hv2[10];
                hv2[0] = okL ? *(const u64*)(hrow + (size_t)(px0-1)*(COUT*2) + ci*2) : 0ULL;
                #pragma unroll
                for (int j = 1; j < 9; j++)
                    hv2[j] = *(const u64*)(hrow + (size_t)(px0-1+j)*(COUT*2) + ci*2);
                hv2[9] = okR ? *(const u64*)(hrow + (size_t)(px0+8)*(COUT*2) + ci*2) : 0ULL;
                #pragma unroll
                for (int kx = 0; kx < 3; kx++) {
                    const size_t widx = ((size_t)(ky*3+kx)*COUT + ci)*32 + lane;
                    ulonglong2 wA = ((const ulonglong2*)wbase)[widx];
                    #pragma unroll
                    for (int p = 0; p < 8; p++) {
                        const u64 s2 = hv2[p + kx];
                        fma_x2(acc[0][p], s2, wA.x);
                        fma_x2(acc[1][p], s2, wA.y);
                    }
                }
            }
        }
    }

    // role 1 deposits gates cc,o; role 0 consumes after barrier.
    if (role == 1) {
        #pragma unroll
        for (int g = 0; g < 2; g++)
            #pragma unroll
            for (int p = 0; p < 8; p++)
                sh[pg][lane][g*8 + p] = acc[g][p];
    }
    __syncthreads();

    if (role == 0) {
        // BN constants for this thread's 2 channels
        float2 gm  = *(const float2*)(gamma + co0);
        float2 bt2 = *(const float2*)(beta  + co0);
        float2 mm  = *(const float2*)(mmean + co0);
        float2 mv  = *(const float2*)(mvar  + co0);
        float2 inv, add;
        inv.x = gm.x * rsqrtf(mv.x + 1e-3f); add.x = bt2.x - mm.x*inv.x;
        inv.y = gm.y * rsqrtf(mv.y + 1e-3f); add.y = bt2.y - mm.y*inv.y;

        const size_t pixrow = ((size_t)b*HH + py)*WW;
        #pragma unroll
        for (int p = 0; p < 8; p++) {
            const size_t pix = pixrow + px0 + p;

            float2 gi = unpack2(acc[0][p]);
            float2 gf = unpack2(acc[1][p]);
            float2 gg = unpack2(sh[pg][lane][p]);       // gate cc
            float2 go = unpack2(sh[pg][lane][8 + p]);   // gate o

            float2 i2, f2, o2;
            i2.x = hsig(gi.x); i2.y = hsig(gi.y);
            f2.x = hsig(gf.x); f2.y = hsig(gf.y);
            o2.x = hsig(go.x); o2.y = hsig(go.y);

            float* __restrict__ cp = g_c + pix*COUT + co0;
            float2 cold = FIRST ? make_float2(0.f,0.f) : *(const float2*)cp;

            float2 cn;
            cn.x = f2.x*cold.x + i2.x*tanhf(gg.x);
            cn.y = f2.y*cold.y + i2.y*tanhf(gg.y);
            *(float2*)cp = cn;

            float2 h2;
            h2.x = o2.x * tanhf(cn.x);
            h2.y = o2.y * tanhf(cn.y);
            *(float4*)(hnewd + pix*(COUT*2) + co0*2) = make_float4(h2.x, h2.x, h2.y, h2.y);

            float2 yv;
            yv.x = h2.x*inv.x + add.x;
            yv.y = h2.y*inv.y + add.y;
            float* __restrict__ yp = y + (gxrow + px0 + p)*COUT + co0;
            *(float2*)yp = yv;
        }
    }
}

extern "C" void kernel_launch(void* const* d_in, const int* in_sizes, int n_in,
                              void* d_out, int out_size)
{
    const float* x      = (const float*)d_in[0];
    const float* wk     = (const float*)d_in[1];
    const float* rw     = (const float*)d_in[2];
    const float* bias   = (const float*)d_in[3];
    const float* gamma  = (const float*)d_in[4];
    const float* beta   = (const float*)d_in[5];
    const float* mmean  = (const float*)d_in[6];
    const float* mvar   = (const float*)d_in[7];
    float* y = (float*)d_out;

    // Prep: transpose/split weights (one-time per launch).
    const int n_prep = 9*COUT*32 + 9*CIN*32;
    prep_weights<<<(n_prep + 127)/128, 128>>>(wk, rw);

    // Phase 1: all input convs. 8192 blocks x 128 threads (32 px each).
    input_conv_kernel<<<BB*TT*HH*2, 128>>>(x, bias);

    // Phase 2: 16 sequential recurrent steps. 512 blocks x 256 threads.
    const int nblk = BB*HH*2;
    step_kernel<true><<<nblk, 256>>>(y, 0, gamma, beta, mmean, mvar);
    for (int t = 1; t < TT; t++) {
        step_kernel<false><<<nblk, 256>>>(y, t, gamma, beta, mmean, mvar);
    }
}

// round 9
// speedup vs baseline: 1.2688x; 1.2688x over previous
#include <cuda_runtime.h>
#include <math.h>

#define BB 4
#define TT 16
#define HH 64
#define WW 64
#define CIN 32
#define COUT 64
#define GG (4*COUT)   // 256 gate channels

typedef unsigned long long u64;

// Scratch: gx for all (b,t) pixels: (B*T*H*W, 256) floats = 268MB
__device__ float g_gx[(size_t)BB*TT*HH*WW*GG];
// Duplicated ping-pong hidden state: each channel stored as {h,h} pair
__device__ float g_h0d[(size_t)BB*HH*WW*COUT*2];
__device__ float g_h1d[(size_t)BB*HH*WW*COUT*2];
// Cell state
__device__ float g_c [(size_t)BB*HH*WW*COUT];
// Split transposed weights: [k][ci][lane(32)][4 floats]
// g01: {g0c0,g0c1,g1c0,g1c1}   g23: {g2c0,g2c1,g3c0,g3c1}   (c0=2*lane)
__device__ float g_rw01[9*COUT*32*4];
__device__ float g_rw23[9*COUT*32*4];
__device__ float g_wk01[9*CIN*32*4];
__device__ float g_wk23[9*CIN*32*4];

__device__ __forceinline__ float hsig(float z) {
    return fminf(fmaxf(0.2f*z + 0.5f, 0.0f), 1.0f);
}

__device__ __forceinline__ void fma_x2(u64& acc, u64 s, u64 w) {
    asm("fma.rn.f32x2 %0, %1, %2, %3;" : "=l"(acc) : "l"(s), "l"(w), "l"(acc));
}
__device__ __forceinline__ u64 pack2(float s) {
    u64 r;
    asm("mov.b64 %0, {%1, %1};" : "=l"(r) : "f"(s));
    return r;
}
__device__ __forceinline__ float2 unpack2(u64 v) {
    float2 f;
    asm("mov.b64 {%0, %1}, %2;" : "=f"(f.x), "=f"(f.y) : "l"(v));
    return f;
}

// ---------------------------------------------------------------------------
// Weight transpose prep.
// ---------------------------------------------------------------------------
__global__ __launch_bounds__(128)
void prep_weights(const float* __restrict__ wk, const float* __restrict__ rw)
{
    const int i = blockIdx.x * 128 + threadIdx.x;
    if (i < 9*COUT*32) {
        const int j  = i & 31;
        const int ci = (i >> 5) & 63;
        const int k  = i >> 11;
        const float* s = rw + ((size_t)(k*COUT + ci))*GG + 2*j;
        ((float4*)g_rw01)[i] = make_float4(s[0],   s[1],   s[64],  s[65]);
        ((float4*)g_rw23)[i] = make_float4(s[128], s[129], s[192], s[193]);
    }
    const int m = i - 9*COUT*32;
    if (m >= 0 && m < 9*CIN*32) {
        const int j  = m & 31;
        const int ci = (m >> 5) & 31;
        const int k  = m >> 10;
        const float* s = wk + ((size_t)(k*CIN + ci))*GG + 2*j;
        ((float4*)g_wk01)[m] = make_float4(s[0],   s[1],   s[64],  s[65]);
        ((float4*)g_wk23)[m] = make_float4(s[128], s[129], s[192], s[193]);
    }
}

// Chunked smem weight tile: [9 taps][4 ci][32 lanes] float4, for each of 2 arrays.
#define CHUNK 4
#define TILE4 (9*CHUNK*32)    // 1152 float4 per array

// ---------------------------------------------------------------------------
// Phase 1: input-to-gate conv with smem-staged weights.
// Thread: 8 pixels x (2 channels x 4 gates) = 32 packed accumulators.
// Block: 128 thr = 4 warps x 32 lanes = 32 px. Grid: B*T*H*2 = 8192.
// ---------------------------------------------------------------------------
__global__ __launch_bounds__(128, 4)
void input_conv_kernel(const float* __restrict__ x,
                       const float* __restrict__ bias)
{
    __shared__ float4 s01[TILE4];
    __shared__ float4 s23[TILE4];

    const int tx   = threadIdx.x;
    const int lane = tx & 31;
    const int co0  = lane * 2;
    const int pg   = tx >> 5;
    const int bid  = blockIdx.x;
    const int bt   = bid >> 7;
    const int r    = bid & 127;
    const int py   = r >> 1;
    const int px0  = (r & 1) * 32 + pg * 8;
    const bool okL = (px0 > 0);
    const bool okR = (px0 < WW - 8);

    u64 acc[4][8];
    #pragma unroll
    for (int g = 0; g < 4; g++) {
        u64 bv = *(const u64*)(bias + g*COUT + co0);
        #pragma unroll
        for (int p = 0; p < 8; p++) acc[g][p] = bv;
    }

    const int iy0 = py - 1;
    const float* __restrict__ xbase = x + ((size_t)(bt*HH))*WW*CIN;

    #pragma unroll 1
    for (int cc = 0; cc < CIN; cc += CHUNK) {
        __syncthreads();
        #pragma unroll
        for (int i = tx; i < TILE4; i += 128) {
            const int tap  = i >> 7;          // /128
            const int rest = i & 127;
            const size_t src = (size_t)(tap*CIN + cc)*32 + rest;
            s01[i] = ((const float4*)g_wk01)[src];
            s23[i] = ((const float4*)g_wk23)[src];
        }
        __syncthreads();

        #pragma unroll
        for (int ky = 0; ky < 3; ky++) {
            const int iy = iy0 + ky;
            if ((unsigned)iy >= HH) continue;
            const float* __restrict__ xrow = xbase + ((size_t)iy*WW)*CIN;
            #pragma unroll
            for (int c4 = 0; c4 < CHUNK; c4++) {
                const int ci = cc + c4;
                u64 hv2[10];
                hv2[0] = okL ? pack2(xrow[(size_t)(px0-1)*CIN + ci]) : 0ULL;
                #pragma unroll
                for (int j = 1; j < 9; j++)
                    hv2[j] = pack2(xrow[(size_t)(px0-1+j)*CIN + ci]);
                hv2[9] = okR ? pack2(xrow[(size_t)(px0+8)*CIN + ci]) : 0ULL;
                #pragma unroll
                for (int kx = 0; kx < 3; kx++) {
                    const int sidx = ((ky*3+kx)*CHUNK + c4)*32 + lane;
                    const ulonglong2 wA = *reinterpret_cast<const ulonglong2*>(&s01[sidx]);
                    const ulonglong2 wB = *reinterpret_cast<const ulonglong2*>(&s23[sidx]);
                    #pragma unroll
                    for (int p = 0; p < 8; p++) {
                        const u64 s2 = hv2[p + kx];
                        fma_x2(acc[0][p], s2, wA.x);
                        fma_x2(acc[1][p], s2, wA.y);
                        fma_x2(acc[2][p], s2, wB.x);
                        fma_x2(acc[3][p], s2, wB.y);
                    }
                }
            }
        }
    }

    const size_t rowbase = ((size_t)bt*HH + py)*WW;
    #pragma unroll
    for (int p = 0; p < 8; p++) {
        float* __restrict__ o = g_gx + (rowbase + px0 + p)*GG + co0;
        *(u64*)(o + 0*COUT) = acc[0][p];
        *(u64*)(o + 1*COUT) = acc[1][p];
        *(u64*)(o + 2*COUT) = acc[2][p];
        *(u64*)(o + 3*COUT) = acc[3][p];
    }
}

// ---------------------------------------------------------------------------
// Phase 2: one recurrent step with smem-staged weights.
// Thread: 8 pixels x (2 channels x 4 gates) = 32 packed accumulators.
// Block: 128 thr = 4 warps x 32 lanes = 32 px. Grid: B*H*2 = 512.
// ---------------------------------------------------------------------------
template<bool FIRST>
__global__ __launch_bounds__(128, 4)
void step_kernel(float* __restrict__ y,
                 const int t,
                 const float* __restrict__ gamma,
                 const float* __restrict__ beta,
                 const float* __restrict__ mmean,
                 const float* __restrict__ mvar)
{
    __shared__ float4 s01[TILE4];
    __shared__ float4 s23[TILE4];

    const float* __restrict__ hprevd = (t & 1) ? g_h0d : g_h1d;
    float*       __restrict__ hnewd  = (t & 1) ? g_h1d : g_h0d;

    const int tx   = threadIdx.x;
    const int lane = tx & 31;
    const int co0  = lane * 2;
    const int pg   = tx >> 5;
    const int bid  = blockIdx.x;
    const int b    = bid >> 7;
    const int r    = bid & 127;
    const int py   = r >> 1;
    const int px0  = (r & 1) * 32 + pg * 8;
    const bool okL = (px0 > 0);
    const bool okR = (px0 < WW - 8);

    u64 acc[4][8];
    const size_t gxrow = ((size_t)(b*TT + t)*HH + py)*WW;
    #pragma unroll
    for (int p = 0; p < 8; p++) {
        const float* __restrict__ gp = g_gx + (gxrow + px0 + p)*GG + co0;
        acc[0][p] = *(const u64*)(gp + 0*COUT);
        acc[1][p] = *(const u64*)(gp + 1*COUT);
        acc[2][p] = *(const u64*)(gp + 2*COUT);
        acc[3][p] = *(const u64*)(gp + 3*COUT);
    }

    if (!FIRST) {
        const int iy0 = py - 1;
        const float* __restrict__ hbase = hprevd + ((size_t)(b*HH))*WW*(COUT*2);

        #pragma unroll 1
        for (int cc = 0; cc < COUT; cc += CHUNK) {
            __syncthreads();
            #pragma unroll
            for (int i = tx; i < TILE4; i += 128) {
                const int tap  = i >> 7;
                const int rest = i & 127;
                const size_t src = (size_t)(tap*COUT + cc)*32 + rest;
                s01[i] = ((const float4*)g_rw01)[src];
                s23[i] = ((const float4*)g_rw23)[src];
            }
            __syncthreads();

            #pragma unroll
            for (int ky = 0; ky < 3; ky++) {
                const int iy = iy0 + ky;
                if ((unsigned)iy >= HH) continue;
                const float* __restrict__ hrow = hbase + ((size_t)iy*WW)*(COUT*2);
                #pragma unroll
                for (int c4 = 0; c4 < CHUNK; c4++) {
                    const int ci = cc + c4;
                    u64 hv2[10];
                    hv2[0] = okL ? *(const u64*)(hrow + (size_t)(px0-1)*(COUT*2) + ci*2) : 0ULL;
                    #pragma unroll
                    for (int j = 1; j < 9; j++)
                        hv2[j] = *(const u64*)(hrow + (size_t)(px0-1+j)*(COUT*2) + ci*2);
                    hv2[9] = okR ? *(const u64*)(hrow + (size_t)(px0+8)*(COUT*2) + ci*2) : 0ULL;
                    #pragma unroll
                    for (int kx = 0; kx < 3; kx++) {
                        const int sidx = ((ky*3+kx)*CHUNK + c4)*32 + lane;
                        const ulonglong2 wA = *reinterpret_cast<const ulonglong2*>(&s01[sidx]);
                        const ulonglong2 wB = *reinterpret_cast<const ulonglong2*>(&s23[sidx]);
                        #pragma unroll
                        for (int p = 0; p < 8; p++) {
                            const u64 s2 = hv2[p + kx];
                            fma_x2(acc[0][p], s2, wA.x);
                            fma_x2(acc[1][p], s2, wA.y);
                            fma_x2(acc[2][p], s2, wB.x);
                            fma_x2(acc[3][p], s2, wB.y);
                        }
                    }
                }
            }
        }
    }

    // BN constants for this thread's 2 channels
    float2 gm  = *(const float2*)(gamma + co0);
    float2 bt2 = *(const float2*)(beta  + co0);
    float2 mm  = *(const float2*)(mmean + co0);
    float2 mv  = *(const float2*)(mvar  + co0);
    float2 inv, add;
    inv.x = gm.x * rsqrtf(mv.x + 1e-3f); add.x = bt2.x - mm.x*inv.x;
    inv.y = gm.y * rsqrtf(mv.y + 1e-3f); add.y = bt2.y - mm.y*inv.y;

    const size_t pixrow = ((size_t)b*HH + py)*WW;
    #pragma unroll
    for (int p = 0; p < 8; p++) {
        const size_t pix = pixrow + px0 + p;

        float2 gi = unpack2(acc[0][p]);
        float2 gf = unpack2(acc[1][p]);
        float2 gg = unpack2(acc[2][p]);
        float2 go = unpack2(acc[3][p]);

        float2 i2, f2, o2;
        i2.x = hsig(gi.x); i2.y = hsig(gi.y);
        f2.x = hsig(gf.x); f2.y = hsig(gf.y);
        o2.x = hsig(go.x); o2.y = hsig(go.y);

        float* __restrict__ cp = g_c + pix*COUT + co0;
        float2 cold = FIRST ? make_float2(0.f,0.f) : *(const float2*)cp;

        float2 cn;
        cn.x = f2.x*cold.x + i2.x*tanhf(gg.x);
        cn.y = f2.y*cold.y + i2.y*tanhf(gg.y);
        *(float2*)cp = cn;

        float2 h2;
        h2.x = o2.x * tanhf(cn.x);
        h2.y = o2.y * tanhf(cn.y);
        *(float4*)(hnewd + pix*(COUT*2) + co0*2) = make_float4(h2.x, h2.x, h2.y, h2.y);

        float2 yv;
        yv.x = h2.x*inv.x + add.x;
        yv.y = h2.y*inv.y + add.y;
        float* __restrict__ yp = y + (gxrow + px0 + p)*COUT + co0;
        *(float2*)yp = yv;
    }
}

extern "C" void kernel_launch(void* const* d_in, const int* in_sizes, int n_in,
                              void* d_out, int out_size)
{
    const float* x      = (const float*)d_in[0];
    const float* wk     = (const float*)d_in[1];
    const float* rw     = (const float*)d_in[2];
    const float* bias   = (const float*)d_in[3];
    const float* gamma  = (const float*)d_in[4];
    const float* beta   = (const float*)d_in[5];
    const float* mmean  = (const float*)d_in[6];
    const float* mvar   = (const float*)d_in[7];
    float* y = (float*)d_out;

    // Prep: transpose/split weights (one-time per launch).
    const int n_prep = 9*COUT*32 + 9*CIN*32;
    prep_weights<<<(n_prep + 127)/128, 128>>>(wk, rw);

    // Phase 1: all input convs. 8192 blocks x 128 threads (32 px each).
    input_conv_kernel<<<BB*TT*HH*2, 128>>>(x, bias);

    // Phase 2: 16 sequential recurrent steps. 512 blocks x 128 threads.
    const int nblk = BB*HH*2;
    step_kernel<true><<<nblk, 128>>>(y, 0, gamma, beta, mmean, mvar);
    for (int t = 1; t < TT; t++) {
        step_kernel<false><<<nblk, 128>>>(y, t, gamma, beta, mmean, mvar);
    }
}